// round 7
// baseline (speedup 1.0000x reference)
#include <cuda_runtime.h>
#include <cuda_bf16.h>
#include <cstdint>

#define N_NODES 100000
#define N_EDGES 1600000
#define D 64
#define SCAN_BLOCKS 391   // ceil(N_NODES/256)

// ---------------- scratch (static device globals; no allocation) ----------------
__device__ __align__(16) float  g_t0[(size_t)N_NODES * D];  // ping
__device__ __align__(16) float  g_t1[(size_t)N_NODES * D];  // pong
__device__ __align__(16) int    g_csr[N_EDGES];             // src ids grouped by dst
__device__ __align__(16) int    g_rowptr[N_NODES + 1];
__device__ __align__(16) int    g_woff[N_NODES];            // fill cursors
__device__ __align__(16) int    g_cnt[N_NODES];             // in-degree histogram
__device__ __align__(16) float  g_deginv[N_NODES];          // 1/max(out_degree,1)
__device__ __align__(16) int    g_bsum[SCAN_BLOCKS];
__device__ __align__(16) int    g_bsum_ex[SCAN_BLOCKS];
__device__ __align__(16) float  g_msum[D];
__device__ int g_is64;

// ---------------- helpers ----------------------------------------------------------
__device__ __forceinline__ int idx_at(const void* __restrict__ p, int e, int is64) {
    return is64 ? (int)((const long long*)p)[e] : ((const int*)p)[e];
}

// ---------------- init: zero histograms + msum; PARALLEL dtype detection -----------
__global__ void gcn_init(const void* __restrict__ src) {
    int i = blockIdx.x * blockDim.x + threadIdx.x;
    if (i < N_NODES) { g_cnt[i] = 0; g_deginv[i] = 0.0f; }
    if (i < D)       g_msum[i] = 0.0f;

    if (blockIdx.x == 0) {  // one load per thread instead of a 256-iter serial loop
        __shared__ int ok;
        if (threadIdx.x == 0) ok = 1;
        __syncthreads();
        long long v = ((const long long*)src)[threadIdx.x];
        if (v < 0 || v >= N_NODES) ok = 0;   // benign race, all writers write 0
        __syncthreads();
        if (threadIdx.x == 0) g_is64 = ok;   // JAX int64 silently -> int32
    }
}

// ---------------- prepass: both histograms ------------------------------------------
__global__ void gcn_prep(const void* __restrict__ src, const void* __restrict__ dst) {
    int e = blockIdx.x * blockDim.x + threadIdx.x;
    if (e >= N_EDGES) return;
    const int is64 = g_is64;
    int s = idx_at(src, e, is64);
    int d = idx_at(dst, e, is64);
    if ((unsigned)s >= N_NODES) s = 0;
    if ((unsigned)d >= N_NODES) d = 0;
    atomicAdd(&g_deginv[s], 1.0f);
    atomicAdd(&g_cnt[d], 1);
}

// ---------------- scan stage 1: per-block sums ----------------------------------------
__global__ __launch_bounds__(256) void gcn_scan1() {
    __shared__ int sh[256];
    int i = blockIdx.x * 256 + threadIdx.x;
    sh[threadIdx.x] = (i < N_NODES) ? g_cnt[i] : 0;
    __syncthreads();
    for (int off = 128; off > 0; off >>= 1) {
        if (threadIdx.x < off) sh[threadIdx.x] += sh[threadIdx.x + off];
        __syncthreads();
    }
    if (threadIdx.x == 0) g_bsum[blockIdx.x] = sh[0];
}

// ---------------- scan stage 2: exclusive scan of block sums (1 block) ----------------
__global__ __launch_bounds__(512) void gcn_scan2() {
    __shared__ int sh[512];
    int t = threadIdx.x;
    int v = (t < SCAN_BLOCKS) ? g_bsum[t] : 0;
    sh[t] = v;
    __syncthreads();
    for (int off = 1; off < 512; off <<= 1) {
        int add = (t >= off) ? sh[t - off] : 0;
        __syncthreads();
        sh[t] += add;
        __syncthreads();
    }
    if (t < SCAN_BLOCKS) g_bsum_ex[t] = sh[t] - v;
    if (t == 511) g_rowptr[N_NODES] = sh[511];
}

// ---------------- scan stage 3: local scan + add-back; fused deg_inv ------------------
__global__ __launch_bounds__(256) void gcn_scan3() {
    __shared__ int sh[256];
    int i = blockIdx.x * 256 + threadIdx.x;
    int t = threadIdx.x;
    int c = (i < N_NODES) ? g_cnt[i] : 0;
    sh[t] = c;
    __syncthreads();
    for (int off = 1; off < 256; off <<= 1) {
        int add = (t >= off) ? sh[t - off] : 0;
        __syncthreads();
        sh[t] += add;
        __syncthreads();
    }
    if (i < N_NODES) {
        int start = g_bsum_ex[blockIdx.x] + sh[t] - c;
        g_rowptr[i] = start;
        g_woff[i]   = start;
        g_deginv[i] = 1.0f / fmaxf(g_deginv[i], 1.0f);
    }
}

// ---------------- fill: csr[pos] = src, grouped by dst ---------------------------------
__global__ void gcn_fill(const void* __restrict__ src, const void* __restrict__ dst) {
    int e = blockIdx.x * blockDim.x + threadIdx.x;
    if (e >= N_EDGES) return;
    const int is64 = g_is64;
    int s = idx_at(src, e, is64);
    int d = idx_at(dst, e, is64);
    if ((unsigned)s >= N_NODES) s = 0;
    if ((unsigned)d >= N_NODES) d = 0;
    int pos = atomicAdd(&g_woff[d], 1);
    g_csr[pos] = s;
}

// ---------------- gather core: sum_{e in CSR[node]} t_in[src(e)][lane] -----------------
__device__ __forceinline__ float4 agg_node(const float* __restrict__ t_in,
                                           int node, int lane) {
    int beg = __ldg(&g_rowptr[node]);
    int end = __ldg(&g_rowptr[node + 1]);
    float4 acc = make_float4(0.f, 0.f, 0.f, 0.f);
    int e = beg;
    for (; e + 4 <= end; e += 4) {
        int s0 = __ldg(&g_csr[e]),   s1 = __ldg(&g_csr[e+1]);
        int s2 = __ldg(&g_csr[e+2]), s3 = __ldg(&g_csr[e+3]);
        float4 v0 = __ldg((const float4*)(t_in + (size_t)s0 * D) + lane);
        float4 v1 = __ldg((const float4*)(t_in + (size_t)s1 * D) + lane);
        float4 v2 = __ldg((const float4*)(t_in + (size_t)s2 * D) + lane);
        float4 v3 = __ldg((const float4*)(t_in + (size_t)s3 * D) + lane);
        acc.x += v0.x + v1.x + v2.x + v3.x;
        acc.y += v0.y + v1.y + v2.y + v3.y;
        acc.z += v0.z + v1.z + v2.z + v3.z;
        acc.w += v0.w + v1.w + v2.w + v3.w;
    }
    for (; e < end; e++) {
        int s = __ldg(&g_csr[e]);
        float4 v = __ldg((const float4*)(t_in + (size_t)s * D) + lane);
        acc.x += v.x; acc.y += v.y; acc.z += v.z; acc.w += v.w;
    }
    return acc;
}

// ---------------- layer 0 GEMM: t0 = (features * deginv) @ W0 --------------------------
// 128 threads, 64 rows, 2 rows x 16 cols per thread.
__global__ __launch_bounds__(128) void gcn_gemm0(
    const float* __restrict__ in, const float* __restrict__ W,
    float* __restrict__ t_out)
{
    __shared__ float Ws[D][D];
    __shared__ float Xs[64][68];

    const int tid = threadIdx.x;
    const int n0  = blockIdx.x * 64;

    {
        const float4* w4 = (const float4*)W;
        float4* ws4 = (float4*)&Ws[0][0];
        #pragma unroll
        for (int i = tid; i < (D * D) / 4; i += 128) ws4[i] = w4[i];
    }
    for (int i = tid; i < 64 * (D / 4); i += 128) {
        int r = i >> 4, q = i & 15;
        int row = n0 + r;
        float4 x = make_float4(0.f, 0.f, 0.f, 0.f);
        if (row < N_NODES) {
            x = __ldg((const float4*)(in + (size_t)row * D) + q);
            float di = g_deginv[row];
            x.x *= di; x.y *= di; x.z *= di; x.w *= di;
        }
        *(float4*)&Xs[r][q * 4] = x;
    }
    __syncthreads();

    const int rb = tid >> 2;
    const int c0 = (tid & 3) * 16;
    float acc0[16], acc1[16];
    #pragma unroll
    for (int i = 0; i < 16; i++) { acc0[i] = 0.f; acc1[i] = 0.f; }

    #pragma unroll
    for (int k = 0; k < D; k++) {
        float x0 = Xs[rb][k];
        float x1 = Xs[rb + 32][k];
        #pragma unroll
        for (int q = 0; q < 4; q++) {
            float4 w = *(const float4*)&Ws[k][c0 + q * 4];
            acc0[q*4+0] += x0 * w.x; acc0[q*4+1] += x0 * w.y;
            acc0[q*4+2] += x0 * w.z; acc0[q*4+3] += x0 * w.w;
            acc1[q*4+0] += x1 * w.x; acc1[q*4+1] += x1 * w.y;
            acc1[q*4+2] += x1 * w.z; acc1[q*4+3] += x1 * w.w;
        }
    }

    int row0 = n0 + rb, row1 = n0 + rb + 32;
    if (row0 < N_NODES) {
        float* o = t_out + (size_t)row0 * D + c0;
        #pragma unroll
        for (int q = 0; q < 4; q++)
            *(float4*)(o + q*4) = make_float4(acc0[q*4+0], acc0[q*4+1],
                                              acc0[q*4+2], acc0[q*4+3]);
    }
    if (row1 < N_NODES) {
        float* o = t_out + (size_t)row1 * D + c0;
        #pragma unroll
        for (int q = 0; q < 4; q++)
            *(float4*)(o + q*4) = make_float4(acc1[q*4+0], acc1[q*4+1],
                                              acc1[q*4+2], acc1[q*4+3]);
    }
}

// ---------------- fused gather + prologue + GEMM (layers 1,2) --------------------------
// t_out[n,:] = ( relu(gather(t_in)[n,:] + bias) * deginv[n] ) @ W
// 256 threads, 64 nodes/block. Phase 1: 16 groups x 16 lanes gather 4 nodes each
// into Xs. Phase 2: 2 rows x 8 cols per thread GEMM.
__global__ __launch_bounds__(256) void gcn_gather_gemm(
    const float* __restrict__ t_in, const float* __restrict__ W,
    const float* __restrict__ bias, float* __restrict__ t_out)
{
    __shared__ float Ws[D][D];      // 16 KB
    __shared__ float Xs[64][68];    // 17.4 KB

    const int tid = threadIdx.x;
    const int n0  = blockIdx.x * 64;

    // W -> smem (1024 float4 / 256 thr = 4 each)
    {
        const float4* w4 = (const float4*)W;
        float4* ws4 = (float4*)&Ws[0][0];
        #pragma unroll
        for (int i = tid; i < (D * D) / 4; i += 256) ws4[i] = w4[i];
    }

    // Phase 1: gather + prologue
    {
        const int gid  = tid >> 4;      // group 0..15
        const int lane = tid & 15;
        const float4 b = __ldg((const float4*)bias + lane);
        #pragma unroll
        for (int i = 0; i < 4; i++) {
            int local = gid * 4 + i;
            int node  = n0 + local;
            float4 x = make_float4(0.f, 0.f, 0.f, 0.f);
            if (node < N_NODES) {
                x = agg_node(t_in, node, lane);
                float di = g_deginv[node];
                x.x = fmaxf(x.x + b.x, 0.f) * di;
                x.y = fmaxf(x.y + b.y, 0.f) * di;
                x.z = fmaxf(x.z + b.z, 0.f) * di;
                x.w = fmaxf(x.w + b.w, 0.f) * di;
            }
            *(float4*)&Xs[local][lane * 4] = x;
        }
    }
    __syncthreads();

    // Phase 2: GEMM, 2 rows x 8 cols per thread
    const int rb = tid >> 3;          // 0..31 -> rows rb, rb+32
    const int c0 = (tid & 7) * 8;
    float acc0[8], acc1[8];
    #pragma unroll
    for (int i = 0; i < 8; i++) { acc0[i] = 0.f; acc1[i] = 0.f; }

    #pragma unroll
    for (int k = 0; k < D; k++) {
        float x0 = Xs[rb][k];
        float x1 = Xs[rb + 32][k];
        float4 wA = *(const float4*)&Ws[k][c0];
        float4 wB = *(const float4*)&Ws[k][c0 + 4];
        acc0[0] += x0 * wA.x; acc0[1] += x0 * wA.y;
        acc0[2] += x0 * wA.z; acc0[3] += x0 * wA.w;
        acc0[4] += x0 * wB.x; acc0[5] += x0 * wB.y;
        acc0[6] += x0 * wB.z; acc0[7] += x0 * wB.w;
        acc1[0] += x1 * wA.x; acc1[1] += x1 * wA.y;
        acc1[2] += x1 * wA.z; acc1[3] += x1 * wA.w;
        acc1[4] += x1 * wB.x; acc1[5] += x1 * wB.y;
        acc1[6] += x1 * wB.z; acc1[7] += x1 * wB.w;
    }

    int row0 = n0 + rb, row1 = n0 + rb + 32;
    if (row0 < N_NODES) {
        float* o = t_out + (size_t)row0 * D + c0;
        *(float4*)(o)     = make_float4(acc0[0], acc0[1], acc0[2], acc0[3]);
        *(float4*)(o + 4) = make_float4(acc0[4], acc0[5], acc0[6], acc0[7]);
    }
    if (row1 < N_NODES) {
        float* o = t_out + (size_t)row1 * D + c0;
        *(float4*)(o)     = make_float4(acc1[0], acc1[1], acc1[2], acc1[3]);
        *(float4*)(o + 4) = make_float4(acc1[4], acc1[5], acc1[6], acc1[7]);
    }
}

// ---------------- final: out = gather(t_in) + b2; fused column sums --------------------
// N_NODES % 16 == 0 -> every thread has a valid node.
__global__ __launch_bounds__(256) void gcn_aggregate_final(
    const float* __restrict__ t_in, const float* __restrict__ b2,
    float* __restrict__ out)
{
    int node = blockIdx.x * 16 + (threadIdx.x >> 4);
    int lane = threadIdx.x & 15;

    float4 acc = agg_node(t_in, node, lane);
    float4 bb  = __ldg((const float4*)b2 + lane);
    acc.x += bb.x; acc.y += bb.y; acc.z += bb.z; acc.w += bb.w;
    *((float4*)(out + (size_t)node * D) + lane) = acc;

    __shared__ float4 sdata[256];
    sdata[threadIdx.x] = acc;
    __syncthreads();
    #pragma unroll
    for (int off = 128; off >= 16; off >>= 1) {
        if (threadIdx.x < off) {
            float4 o = sdata[threadIdx.x + off];
            sdata[threadIdx.x].x += o.x; sdata[threadIdx.x].y += o.y;
            sdata[threadIdx.x].z += o.z; sdata[threadIdx.x].w += o.w;
        }
        __syncthreads();
    }
    if (threadIdx.x < 16) {
        float4 s = sdata[threadIdx.x];
        atomicAdd(&g_msum[threadIdx.x * 4 + 0], s.x);
        atomicAdd(&g_msum[threadIdx.x * 4 + 1], s.y);
        atomicAdd(&g_msum[threadIdx.x * 4 + 2], s.z);
        atomicAdd(&g_msum[threadIdx.x * 4 + 3], s.w);
    }
}

__global__ void gcn_mean_write(float* __restrict__ out) {
    int j = threadIdx.x;
    if (j < D) out[(size_t)N_NODES * D + j] = g_msum[j] / (float)N_NODES;
}

// ---------------- launch -----------------------------------------------------------------
extern "C" void kernel_launch(void* const* d_in, const int* in_sizes, int n_in,
                              void* d_out, int out_size)
{
    const float* features = (const float*)d_in[0];
    const void*  src      = d_in[1];
    const void*  dst      = d_in[2];
    const float* W0 = (const float*)d_in[3];
    // b0 = d_in[4]
    const float* W1 = (const float*)d_in[5];
    const float* b0 = (const float*)d_in[4];
    const float* b1 = (const float*)d_in[6];
    const float* W2 = (const float*)d_in[7];
    const float* b2 = (const float*)d_in[8];
    float* out = (float*)d_out;

    const int threads      = 256;
    const int blocks_edges = (N_EDGES + threads - 1) / threads;   // 6250
    const int blocks_gemm  = (N_NODES + 63) / 64;                 // 1563
    const int blocks_agg   = N_NODES / 16;                        // 6250 (exact)

    float* t0; float* t1;
    cudaGetSymbolAddress((void**)&t0, g_t0);   // address lookup only (no alloc)
    cudaGetSymbolAddress((void**)&t1, g_t1);

    // CSR build + degrees
    gcn_init<<<SCAN_BLOCKS, threads>>>(src);
    gcn_prep<<<blocks_edges, threads>>>(src, dst);
    gcn_scan1<<<SCAN_BLOCKS, 256>>>();
    gcn_scan2<<<1, 512>>>();
    gcn_scan3<<<SCAN_BLOCKS, 256>>>();
    gcn_fill<<<blocks_edges, threads>>>(src, dst);

    // layer 0: t0 = (features*deginv)@W0
    gcn_gemm0<<<blocks_gemm, 128>>>(features, W0, t0);
    // layer 1: t1 = (relu(gather(t0)+b0)*deginv)@W1
    gcn_gather_gemm<<<blocks_gemm, threads>>>(t0, W1, b0, t1);
    // layer 2: t0 = (relu(gather(t1)+b1)*deginv)@W2
    gcn_gather_gemm<<<blocks_gemm, threads>>>(t1, W2, b1, t0);
    // output: out = gather(t0) + b2 ; mean
    gcn_aggregate_final<<<blocks_agg, threads>>>(t0, b2, out);
    gcn_mean_write<<<1, 64>>>(out);
}

// round 8
// speedup vs baseline: 1.0063x; 1.0063x over previous
#include <cuda_runtime.h>
#include <cuda_bf16.h>
#include <cstdint>

#define N_NODES 100000
#define N_EDGES 1600000
#define D 64
#define SCAN_BLOCKS 391   // ceil(N_NODES/256)

// ---------------- scratch (static device globals; no allocation) ----------------
__device__ __align__(16) float  g_t[(size_t)N_NODES * D];   // transformed features
__device__ __align__(16) float  g_agg[(size_t)N_NODES * D]; // aggregation output
__device__ __align__(16) int    g_csr[N_EDGES];             // src ids grouped by dst
__device__ __align__(16) int    g_rowptr[N_NODES + 1];
__device__ __align__(16) int    g_woff[N_NODES];            // fill cursors
__device__ __align__(16) int    g_cnt[N_NODES];             // in-degree histogram
__device__ __align__(16) float  g_deginv[N_NODES];          // 1/max(out_degree,1)
__device__ __align__(16) int    g_bsum[SCAN_BLOCKS];
__device__ __align__(16) int    g_bsum_ex[SCAN_BLOCKS];
__device__ __align__(16) float  g_msum[D];
__device__ int g_is64;

// ---------------- helpers ----------------------------------------------------------
__device__ __forceinline__ int idx_at(const void* __restrict__ p, int e, int is64) {
    return is64 ? (int)((const long long*)p)[e] : ((const int*)p)[e];
}

// ---------------- init: zero histograms + msum; PARALLEL dtype detection -----------
__global__ void gcn_init(const void* __restrict__ src) {
    int i = blockIdx.x * blockDim.x + threadIdx.x;
    if (i < N_NODES) { g_cnt[i] = 0; g_deginv[i] = 0.0f; }
    if (i < D)       g_msum[i] = 0.0f;

    if (blockIdx.x == 0) {  // 256 parallel loads, not a serial 256-deep chain
        __shared__ int ok;
        if (threadIdx.x == 0) ok = 1;
        __syncthreads();
        long long v = ((const long long*)src)[threadIdx.x];
        if (v < 0 || v >= N_NODES) ok = 0;   // benign race, all writers write 0
        __syncthreads();
        if (threadIdx.x == 0) g_is64 = ok;   // JAX int64 silently -> int32
    }
}

// ---------------- prepass: both histograms; 4 edges/thread (int4 when int32) --------
__global__ void gcn_prep(const void* __restrict__ src, const void* __restrict__ dst) {
    int q = blockIdx.x * blockDim.x + threadIdx.x;   // quad index
    int e0 = q * 4;
    if (e0 >= N_EDGES) return;
    const int is64 = g_is64;
    int s[4], d[4];
    if (!is64) {
        int4 sv = __ldg((const int4*)src + q);
        int4 dv = __ldg((const int4*)dst + q);
        s[0]=sv.x; s[1]=sv.y; s[2]=sv.z; s[3]=sv.w;
        d[0]=dv.x; d[1]=dv.y; d[2]=dv.z; d[3]=dv.w;
    } else {
        #pragma unroll
        for (int i = 0; i < 4; i++) {
            s[i] = (int)((const long long*)src)[e0 + i];
            d[i] = (int)((const long long*)dst)[e0 + i];
        }
    }
    #pragma unroll
    for (int i = 0; i < 4; i++) {
        int ss = ((unsigned)s[i] < N_NODES) ? s[i] : 0;
        int dd = ((unsigned)d[i] < N_NODES) ? d[i] : 0;
        atomicAdd(&g_deginv[ss], 1.0f);
        atomicAdd(&g_cnt[dd], 1);
    }
}

// ---------------- scan stage 1: per-block sums ----------------------------------------
__global__ __launch_bounds__(256) void gcn_scan1() {
    __shared__ int sh[256];
    int i = blockIdx.x * 256 + threadIdx.x;
    sh[threadIdx.x] = (i < N_NODES) ? g_cnt[i] : 0;
    __syncthreads();
    for (int off = 128; off > 0; off >>= 1) {
        if (threadIdx.x < off) sh[threadIdx.x] += sh[threadIdx.x + off];
        __syncthreads();
    }
    if (threadIdx.x == 0) g_bsum[blockIdx.x] = sh[0];
}

// ---------------- scan stage 2: exclusive scan of block sums (1 block) ----------------
__global__ __launch_bounds__(512) void gcn_scan2() {
    __shared__ int sh[512];
    int t = threadIdx.x;
    int v = (t < SCAN_BLOCKS) ? g_bsum[t] : 0;
    sh[t] = v;
    __syncthreads();
    for (int off = 1; off < 512; off <<= 1) {
        int add = (t >= off) ? sh[t - off] : 0;
        __syncthreads();
        sh[t] += add;
        __syncthreads();
    }
    if (t < SCAN_BLOCKS) g_bsum_ex[t] = sh[t] - v;
    if (t == 511) g_rowptr[N_NODES] = sh[511];
}

// ---------------- scan stage 3: local scan + add-back; fused deg_inv ------------------
__global__ __launch_bounds__(256) void gcn_scan3() {
    __shared__ int sh[256];
    int i = blockIdx.x * 256 + threadIdx.x;
    int t = threadIdx.x;
    int c = (i < N_NODES) ? g_cnt[i] : 0;
    sh[t] = c;
    __syncthreads();
    for (int off = 1; off < 256; off <<= 1) {
        int add = (t >= off) ? sh[t - off] : 0;
        __syncthreads();
        sh[t] += add;
        __syncthreads();
    }
    if (i < N_NODES) {
        int start = g_bsum_ex[blockIdx.x] + sh[t] - c;
        g_rowptr[i] = start;
        g_woff[i]   = start;
        g_deginv[i] = 1.0f / fmaxf(g_deginv[i], 1.0f);
    }
}

// ---------------- fill: csr[pos] = src, grouped by dst; 4 edges/thread ----------------
__global__ void gcn_fill(const void* __restrict__ src, const void* __restrict__ dst) {
    int q = blockIdx.x * blockDim.x + threadIdx.x;
    int e0 = q * 4;
    if (e0 >= N_EDGES) return;
    const int is64 = g_is64;
    int s[4], d[4];
    if (!is64) {
        int4 sv = __ldg((const int4*)src + q);
        int4 dv = __ldg((const int4*)dst + q);
        s[0]=sv.x; s[1]=sv.y; s[2]=sv.z; s[3]=sv.w;
        d[0]=dv.x; d[1]=dv.y; d[2]=dv.z; d[3]=dv.w;
    } else {
        #pragma unroll
        for (int i = 0; i < 4; i++) {
            s[i] = (int)((const long long*)src)[e0 + i];
            d[i] = (int)((const long long*)dst)[e0 + i];
        }
    }
    #pragma unroll
    for (int i = 0; i < 4; i++) {
        int ss = ((unsigned)s[i] < N_NODES) ? s[i] : 0;
        int dd = ((unsigned)d[i] < N_NODES) ? d[i] : 0;
        int pos = atomicAdd(&g_woff[dd], 1);
        g_csr[pos] = ss;
    }
}

// ---------------- fused prologue + GEMM, 2 rows x 16 cols per thread -------------------
// g_t[n,:] = prologue(in[n,:]) @ W ; prologue(x) = (relu(x+bias))? * deg_inv[n]
__global__ __launch_bounds__(128) void gcn_gemm(
    const float* __restrict__ in_ext, const float* __restrict__ W,
    const float* __restrict__ bias, int use_relu)
{
    __shared__ float Ws[D][D];
    __shared__ float Xs[64][68];

    const float* in = in_ext ? in_ext : g_agg;
    const int tid = threadIdx.x;
    const int n0  = blockIdx.x * 64;

    {
        const float4* w4 = (const float4*)W;
        float4* ws4 = (float4*)&Ws[0][0];
        #pragma unroll
        for (int i = tid; i < (D * D) / 4; i += 128) ws4[i] = w4[i];
    }
    for (int i = tid; i < 64 * (D / 4); i += 128) {
        int r = i >> 4, q = i & 15;
        int row = n0 + r;
        float4 x = make_float4(0.f, 0.f, 0.f, 0.f);
        if (row < N_NODES) {
            x = __ldg((const float4*)(in + (size_t)row * D) + q);
            if (use_relu) {
                float4 b = __ldg((const float4*)bias + q);
                x.x = fmaxf(x.x + b.x, 0.f); x.y = fmaxf(x.y + b.y, 0.f);
                x.z = fmaxf(x.z + b.z, 0.f); x.w = fmaxf(x.w + b.w, 0.f);
            }
            float di = g_deginv[row];
            x.x *= di; x.y *= di; x.z *= di; x.w *= di;
        }
        *(float4*)&Xs[r][q * 4] = x;
    }
    __syncthreads();

    const int rb = tid >> 2;
    const int c0 = (tid & 3) * 16;
    float acc0[16], acc1[16];
    #pragma unroll
    for (int i = 0; i < 16; i++) { acc0[i] = 0.f; acc1[i] = 0.f; }

    #pragma unroll
    for (int k = 0; k < D; k++) {
        float x0 = Xs[rb][k];
        float x1 = Xs[rb + 32][k];
        #pragma unroll
        for (int q = 0; q < 4; q++) {
            float4 w = *(const float4*)&Ws[k][c0 + q * 4];
            acc0[q*4+0] += x0 * w.x; acc0[q*4+1] += x0 * w.y;
            acc0[q*4+2] += x0 * w.z; acc0[q*4+3] += x0 * w.w;
            acc1[q*4+0] += x1 * w.x; acc1[q*4+1] += x1 * w.y;
            acc1[q*4+2] += x1 * w.z; acc1[q*4+3] += x1 * w.w;
        }
    }

    int row0 = n0 + rb, row1 = n0 + rb + 32;
    if (row0 < N_NODES) {
        float* o = g_t + (size_t)row0 * D + c0;
        #pragma unroll
        for (int q = 0; q < 4; q++)
            *(float4*)(o + q*4) = make_float4(acc0[q*4+0], acc0[q*4+1],
                                              acc0[q*4+2], acc0[q*4+3]);
    }
    if (row1 < N_NODES) {
        float* o = g_t + (size_t)row1 * D + c0;
        #pragma unroll
        for (int q = 0; q < 4; q++)
            *(float4*)(o + q*4) = make_float4(acc1[q*4+0], acc1[q*4+1],
                                              acc1[q*4+2], acc1[q*4+3]);
    }
}

// ---------------- gather core with 8-edge batches (MLP=8) ------------------------------
__device__ __forceinline__ float4 agg_node(int node, int lane) {
    int beg = __ldg(&g_rowptr[node]);
    int end = __ldg(&g_rowptr[node + 1]);
    float4 acc = make_float4(0.f, 0.f, 0.f, 0.f);
    int e = beg;
    for (; e + 8 <= end; e += 8) {
        int s[8];
        #pragma unroll
        for (int i = 0; i < 8; i++) s[i] = __ldg(&g_csr[e + i]);
        float4 v[8];
        #pragma unroll
        for (int i = 0; i < 8; i++)
            v[i] = __ldg((const float4*)(g_t + (size_t)s[i] * D) + lane);
        #pragma unroll
        for (int i = 0; i < 8; i++) {
            acc.x += v[i].x; acc.y += v[i].y; acc.z += v[i].z; acc.w += v[i].w;
        }
    }
    if (e + 4 <= end) {
        int s[4];
        #pragma unroll
        for (int i = 0; i < 4; i++) s[i] = __ldg(&g_csr[e + i]);
        float4 v[4];
        #pragma unroll
        for (int i = 0; i < 4; i++)
            v[i] = __ldg((const float4*)(g_t + (size_t)s[i] * D) + lane);
        #pragma unroll
        for (int i = 0; i < 4; i++) {
            acc.x += v[i].x; acc.y += v[i].y; acc.z += v[i].z; acc.w += v[i].w;
        }
        e += 4;
    }
    for (; e < end; e++) {
        int s = __ldg(&g_csr[e]);
        float4 v = __ldg((const float4*)(g_t + (size_t)s * D) + lane);
        acc.x += v.x; acc.y += v.y; acc.z += v.z; acc.w += v.w;
    }
    return acc;
}

// ---------------- aggregate (layers 0,1): writes g_agg ---------------------------------
__global__ __launch_bounds__(256) void gcn_aggregate()
{
    int node = blockIdx.x * 16 + (threadIdx.x >> 4);
    int lane = threadIdx.x & 15;
    if (node >= N_NODES) return;
    float4 acc = agg_node(node, lane);
    *((float4*)(g_agg + (size_t)node * D) + lane) = acc;
}

// ---------------- aggregate final (layer 2): +b2, write out, fused column sums ---------
__global__ __launch_bounds__(256) void gcn_aggregate_final(
    const float* __restrict__ b2, float* __restrict__ out)
{
    int node = blockIdx.x * 16 + (threadIdx.x >> 4);
    int lane = threadIdx.x & 15;

    float4 acc = agg_node(node, lane);
    float4 bb  = __ldg((const float4*)b2 + lane);
    acc.x += bb.x; acc.y += bb.y; acc.z += bb.z; acc.w += bb.w;
    *((float4*)(out + (size_t)node * D) + lane) = acc;

    __shared__ float4 sdata[256];
    sdata[threadIdx.x] = acc;
    __syncthreads();
    #pragma unroll
    for (int off = 128; off >= 16; off >>= 1) {
        if (threadIdx.x < off) {
            float4 o = sdata[threadIdx.x + off];
            sdata[threadIdx.x].x += o.x; sdata[threadIdx.x].y += o.y;
            sdata[threadIdx.x].z += o.z; sdata[threadIdx.x].w += o.w;
        }
        __syncthreads();
    }
    if (threadIdx.x < 16) {
        float4 s = sdata[threadIdx.x];
        atomicAdd(&g_msum[threadIdx.x * 4 + 0], s.x);
        atomicAdd(&g_msum[threadIdx.x * 4 + 1], s.y);
        atomicAdd(&g_msum[threadIdx.x * 4 + 2], s.z);
        atomicAdd(&g_msum[threadIdx.x * 4 + 3], s.w);
    }
}

__global__ void gcn_mean_write(float* __restrict__ out) {
    int j = threadIdx.x;
    if (j < D) out[(size_t)N_NODES * D + j] = g_msum[j] / (float)N_NODES;
}

// ---------------- launch -----------------------------------------------------------------
extern "C" void kernel_launch(void* const* d_in, const int* in_sizes, int n_in,
                              void* d_out, int out_size)
{
    const float* features = (const float*)d_in[0];
    const void*  src      = d_in[1];
    const void*  dst      = d_in[2];
    const float* W0 = (const float*)d_in[3];
    const float* b0 = (const float*)d_in[4];
    const float* W1 = (const float*)d_in[5];
    const float* b1 = (const float*)d_in[6];
    const float* W2 = (const float*)d_in[7];
    const float* b2 = (const float*)d_in[8];
    float* out = (float*)d_out;

    const int threads      = 256;
    const int blocks_quad  = (N_EDGES / 4 + threads - 1) / threads;  // 1563
    const int blocks_gemm  = (N_NODES + 63) / 64;                    // 1563
    const int blocks_agg   = N_NODES / 16;                           // 6250 (exact)

    // CSR build + degrees
    gcn_init<<<SCAN_BLOCKS, threads>>>(src);
    gcn_prep<<<blocks_quad, threads>>>(src, dst);
    gcn_scan1<<<SCAN_BLOCKS, 256>>>();
    gcn_scan2<<<1, 512>>>();
    gcn_scan3<<<SCAN_BLOCKS, 256>>>();
    gcn_fill<<<blocks_quad, threads>>>(src, dst);

    // layer 0
    gcn_gemm<<<blocks_gemm, 128>>>(features, W0, nullptr, 0);
    gcn_aggregate<<<blocks_agg, threads>>>();
    // layer 1
    gcn_gemm<<<blocks_gemm, 128>>>(nullptr, W1, b0, 1);
    gcn_aggregate<<<blocks_agg, threads>>>();
    // layer 2 (epilogue fused into aggregate)
    gcn_gemm<<<blocks_gemm, 128>>>(nullptr, W2, b1, 1);
    gcn_aggregate_final<<<blocks_agg, threads>>>(b2, out);

    gcn_mean_write<<<1, 64>>>(out);
}